// round 5
// baseline (speedup 1.0000x reference)
#include <cuda_runtime.h>
#include <cuda_bf16.h>
#include <cstdint>

#define L_SEQ 512
#define BATCH 64
#define HID   256
#define EMB   256
#define NTAG  12

// ---------------- device scratch (static: no runtime allocation) ------------
__device__ __align__(256) float g_pre [2u*L_SEQ*1024u*BATCH]; // [dir][l][j][b]
__device__ __align__(256) float g_hall[2u*L_SEQ*BATCH*HID];   // [dir][l][b][u]
__device__ __align__(256) float g_emit[L_SEQ*BATCH*NTAG];     // [l][b][t]
__device__ float    g_nll[BATCH];
__device__ unsigned g_barc[128];                              // 4 groups, padded

// ---------------- K0: reset barrier counters --------------------------------
__global__ void k0_init() {
    if (threadIdx.x < 128) g_barc[threadIdx.x] = 0u;
}

// ---------------- K1: fused gather + input GEMM + bias ----------------------
__global__ void __launch_bounds__(256) k1_pregemm(
    const int*   __restrict__ sentences,
    const float* __restrict__ emb,
    const float* __restrict__ Wf, const float* __restrict__ bf,
    const float* __restrict__ Wb, const float* __restrict__ bb)
{
    __shared__ float Xs[32][68];
    __shared__ float Ws[32][68];
    __shared__ int   toks[64];

    const int jt  = blockIdx.x;   // 0..15
    const int l   = blockIdx.y;   // 0..511
    const int dir = blockIdx.z;   // 0..1
    const float* __restrict__ W    = dir ? Wb : Wf;
    const float* __restrict__ bias = dir ? bb : bf;
    const int tid = threadIdx.x;

    if (tid < 64) toks[tid] = sentences[tid * L_SEQ + l];
    __syncthreads();

    const int tx = tid & 15;
    const int ty = tid >> 4;

    float4 acc0 = make_float4(0,0,0,0);
    float4 acc1 = acc0, acc2 = acc0, acc3 = acc0;

    for (int k0 = 0; k0 < EMB; k0 += 32) {
        #pragma unroll
        for (int i = 0; i < 2; i++) {
            int e = i*256 + tid;
            int r = e >> 3;
            int q = e & 7;
            float4 xv = *(const float4*)(emb + (size_t)toks[r]*EMB + k0 + q*4);
            Xs[q*4+0][r] = xv.x; Xs[q*4+1][r] = xv.y;
            Xs[q*4+2][r] = xv.z; Xs[q*4+3][r] = xv.w;
            float4 wv = *(const float4*)(W + (size_t)(jt*64 + r)*EMB + k0 + q*4);
            Ws[q*4+0][r] = wv.x; Ws[q*4+1][r] = wv.y;
            Ws[q*4+2][r] = wv.z; Ws[q*4+3][r] = wv.w;
        }
        __syncthreads();
        #pragma unroll
        for (int kk = 0; kk < 32; kk++) {
            float4 xv = *(const float4*)&Xs[kk][ty*4];
            float4 wv = *(const float4*)&Ws[kk][tx*4];
            acc0.x += wv.x*xv.x; acc0.y += wv.x*xv.y; acc0.z += wv.x*xv.z; acc0.w += wv.x*xv.w;
            acc1.x += wv.y*xv.x; acc1.y += wv.y*xv.y; acc1.z += wv.y*xv.z; acc1.w += wv.y*xv.w;
            acc2.x += wv.z*xv.x; acc2.y += wv.z*xv.y; acc2.z += wv.z*xv.z; acc2.w += wv.z*xv.w;
            acc3.x += wv.w*xv.x; acc3.y += wv.w*xv.y; acc3.z += wv.w*xv.z; acc3.w += wv.w*xv.w;
        }
        __syncthreads();
    }

    const int jb = jt*64 + tx*4;
    float4 bv = *(const float4*)(bias + jb);
    acc0.x += bv.x; acc0.y += bv.x; acc0.z += bv.x; acc0.w += bv.x;
    acc1.x += bv.y; acc1.y += bv.y; acc1.z += bv.y; acc1.w += bv.y;
    acc2.x += bv.z; acc2.y += bv.z; acc2.z += bv.z; acc2.w += bv.z;
    acc3.x += bv.w; acc3.y += bv.w; acc3.z += bv.w; acc3.w += bv.w;

    size_t base = ((size_t)(dir*L_SEQ + l)*1024u + jt*64) * 64u;
    *(float4*)(g_pre + base + (size_t)(tx*4+0)*64 + ty*4) = acc0;
    *(float4*)(g_pre + base + (size_t)(tx*4+1)*64 + ty*4) = acc1;
    *(float4*)(g_pre + base + (size_t)(tx*4+2)*64 + ty*4) = acc2;
    *(float4*)(g_pre + base + (size_t)(tx*4+3)*64 + ty*4) = acc3;
}

// ---------------- K2: persistent bi-directional LSTM ------------------------
#define K2_SMEM_BYTES ((8256 + 8448 + 288) * 4)   // 67968

__device__ __forceinline__ void group_barrier(unsigned* ctr, unsigned target) {
    __syncthreads();
    if (threadIdx.x == 0) {
        unsigned one = 1u;
        asm volatile("red.release.gpu.global.add.u32 [%0], %1;"
                     :: "l"(ctr), "r"(one) : "memory");
        unsigned v;
        do {
            asm volatile("ld.acquire.gpu.global.u32 %0, [%1];"
                         : "=r"(v) : "l"(ctr) : "memory");
        } while (v < target);
    }
    __syncthreads();
}

__global__ void __launch_bounds__(256, 1) k2_lstm(
    const float* __restrict__ Whhf, const float* __restrict__ Whhb)
{
    extern __shared__ float sm[];
    float2* Wsh  = (float2*)sm;                 // [(gate*8+uu)*129 + kk]
    float2* hsh  = (float2*)(sm + 8256);        // [kk*33 + b]
    float*  hnew = sm + 8256 + 8448;            // [b*9 + u]

    const int tid  = threadIdx.x;
    const int bid  = blockIdx.x;
    const int dir  = bid >> 6;
    const int sub  = bid & 63;
    const int u0   = (sub >> 1) * 8;
    const int bt   = sub & 1;
    const int b0   = bt * 32;
    const int lane = tid & 31;
    const int w    = tid >> 5;
    const int u    = u0 + w;
    const int b    = b0 + lane;
    unsigned* ctr  = &g_barc[(dir*2 + bt) * 32];

    const float* __restrict__ Whh = dir ? Whhb : Whhf;
    float*       hall = g_hall + (size_t)dir * (L_SEQ*BATCH*HID);
    const float* gpre = g_pre  + (size_t)dir * ((size_t)L_SEQ*1024u*BATCH);

    // persistent W_hh slice: 32 rows (4 gates x 8 u) x 256 k
    #pragma unroll
    for (int i = 0; i < 16; i++) {
        int e = i*256 + tid;
        int row = e >> 7;
        int kk  = e & 127;
        int gate = row >> 3, uu = row & 7;
        Wsh[(gate*8+uu)*129 + kk] =
            *(const float2*)(Whh + (size_t)(gate*256 + u0 + uu)*HID + 2*kk);
    }

    const float2* w0p = Wsh + (0*8 + w)*129;
    const float2* w1p = Wsh + (1*8 + w)*129;
    const float2* w2p = Wsh + (2*8 + w)*129;
    const float2* w3p = Wsh + (3*8 + w)*129;

    float c = 0.f;

    for (int s = 0; s < L_SEQ; s++) {
        const int l = dir ? (L_SEQ-1 - s) : s;
        __syncthreads();   // prior hsh/hnew consumers done (also covers W init)

        if (s > 0) {
            const int lp = dir ? (l+1) : (l-1);
            const float* hp = hall + ((size_t)lp*BATCH + b0)*HID;
            #pragma unroll
            for (int i = 0; i < 16; i++) {
                int e  = i*256 + tid;
                int bb = e >> 7;
                int kk = e & 127;
                hsh[kk*33 + bb] = *(const float2*)(hp + bb*HID + 2*kk);
            }
        }
        const float* gp = gpre + (size_t)l*1024u*64u;
        float gi = gp[(0*256+u)*64 + b];
        float gf = gp[(1*256+u)*64 + b];
        float gg = gp[(2*256+u)*64 + b];
        float go = gp[(3*256+u)*64 + b];
        __syncthreads();

        if (s > 0) {
            float a0=0.f, a1=0.f, a2=0.f, a3=0.f;
            #pragma unroll 4
            for (int kk = 0; kk < 128; kk++) {
                float2 h2 = hsh[kk*33 + lane];
                float2 v0 = w0p[kk]; a0 += h2.x*v0.x + h2.y*v0.y;
                float2 v1 = w1p[kk]; a1 += h2.x*v1.x + h2.y*v1.y;
                float2 v2 = w2p[kk]; a2 += h2.x*v2.x + h2.y*v2.y;
                float2 v3 = w3p[kk]; a3 += h2.x*v3.x + h2.y*v3.y;
            }
            gi += a0; gf += a1; gg += a2; go += a3;
        }

        float si = 1.f/(1.f + __expf(-gi));
        float sf = 1.f/(1.f + __expf(-gf));
        float so = 1.f/(1.f + __expf(-go));
        c = sf*c + si*tanhf(gg);
        float h = so*tanhf(c);

        hnew[lane*9 + w] = h;
        __syncthreads();
        {
            int bb = tid >> 3, ww = tid & 7;
            hall[((size_t)l*BATCH + b0 + bb)*HID + u0 + ww] = hnew[bb*9 + ww];
        }
        group_barrier(ctr, 32u*(unsigned)(s+1));
    }
}

// ---------------- K3: emit = [h_f, h_b] @ W_emit^T + b ----------------------
#define K3_SMEM_BYTES ((512*65 + NTAG*512 + 16) * 4)   // 157760

__global__ void __launch_bounds__(256) k3_emit(
    const float* __restrict__ W_emit, const float* __restrict__ b_emit)
{
    extern __shared__ float sm[];
    float* hs = sm;                    // [k*65 + b], k in 0..511
    float* Ws = sm + 512*65;           // [t*512 + k]
    float* bs = Ws + NTAG*512;

    const int l   = blockIdx.x;
    const int tid = threadIdx.x;
    const size_t HOFF = (size_t)L_SEQ*BATCH*HID;

    for (int i = tid; i < NTAG*512; i += 256) Ws[i] = W_emit[i];
    if (tid < NTAG) bs[tid] = b_emit[tid];

    const float* h0 = g_hall + (size_t)l*BATCH*HID;
    for (int e = tid; e < 32768; e += 256) {
        int b = e >> 9;
        int k = e & 511;
        float v = (k < 256) ? h0[(size_t)b*HID + k]
                            : h0[HOFF + (size_t)b*HID + (k-256)];
        hs[k*65 + b] = v;
    }
    __syncthreads();

    for (int o = tid; o < BATCH*NTAG; o += 256) {
        int t = o >> 6;       // 0..11
        int b = o & 63;
        const float* wt = Ws + t*512;
        float acc = bs[t];
        #pragma unroll 8
        for (int k = 0; k < 512; k++) acc += hs[k*65 + b] * wt[k];
        g_emit[(size_t)l*BATCH*NTAG + b*NTAG + t] = acc;
    }
}

// ---------------- K4: CRF forward + gold score per batch --------------------
__global__ void __launch_bounds__(32) k4_crf(
    const int* __restrict__ tags, const float* __restrict__ trans)
{
    const int b    = blockIdx.x;
    const int lane = threadIdx.x;
    const int tc   = (lane < NTAG) ? lane : 0;

    float tcol[NTAG];
    #pragma unroll
    for (int p = 0; p < NTAG; p++) tcol[p] = trans[p*NTAG + tc];

    float alpha = g_emit[b*NTAG + tc];

    for (int l = 1; l < L_SEQ; l++) {
        float v[NTAG];
        float m = -1e30f;
        #pragma unroll
        for (int p = 0; p < NTAG; p++) {
            float ap = __shfl_sync(0xffffffffu, alpha, p);
            v[p] = ap + tcol[p];
            m = fmaxf(m, v[p]);
        }
        float ssum = 0.f;
        #pragma unroll
        for (int p = 0; p < NTAG; p++) ssum += __expf(v[p] - m);
        alpha = m + __logf(ssum) + g_emit[(size_t)l*BATCH*NTAG + b*NTAG + tc];
    }

    // logZ = logsumexp over lanes 0..11
    float av = (lane < NTAG) ? alpha : -1e30f;
    float m = av;
    #pragma unroll
    for (int off = 16; off; off >>= 1)
        m = fmaxf(m, __shfl_xor_sync(0xffffffffu, m, off));
    float s = (lane < NTAG) ? __expf(av - m) : 0.f;
    #pragma unroll
    for (int off = 16; off; off >>= 1)
        s += __shfl_xor_sync(0xffffffffu, s, off);
    float logZ = m + __logf(s);

    // gold score
    float eg = 0.f, tg = 0.f;
    for (int l = lane; l < L_SEQ; l += 32) {
        int tcur = tags[b*L_SEQ + l];
        eg += g_emit[(size_t)l*BATCH*NTAG + b*NTAG + tcur];
        if (l > 0) {
            int tprev = tags[b*L_SEQ + l - 1];
            tg += trans[tprev*NTAG + tcur];
        }
    }
    #pragma unroll
    for (int off = 16; off; off >>= 1) {
        eg += __shfl_xor_sync(0xffffffffu, eg, off);
        tg += __shfl_xor_sync(0xffffffffu, tg, off);
    }

    if (lane == 0) g_nll[b] = logZ - eg - tg;
}

// ---------------- K5: deterministic mean ------------------------------------
__global__ void k5_final(float* out) {
    if (threadIdx.x == 0) {
        float acc = 0.f;
        for (int i = 0; i < BATCH; i++) acc += g_nll[i];
        out[0] = acc / (float)BATCH;
    }
}

// ---------------- launch -----------------------------------------------------
extern "C" void kernel_launch(void* const* d_in, const int* in_sizes, int n_in,
                              void* d_out, int out_size) {
    const int*   sentences = (const int*)  d_in[0];
    const int*   tags      = (const int*)  d_in[1];
    const float* embedding = (const float*)d_in[2];
    const float* W_ih_f    = (const float*)d_in[3];
    const float* W_hh_f    = (const float*)d_in[4];
    const float* b_f       = (const float*)d_in[5];
    const float* W_ih_b    = (const float*)d_in[6];
    const float* W_hh_b    = (const float*)d_in[7];
    const float* b_b       = (const float*)d_in[8];
    const float* W_emit    = (const float*)d_in[9];
    const float* b_emit    = (const float*)d_in[10];
    const float* transition= (const float*)d_in[11];
    float* out = (float*)d_out;

    static bool attr_done = false;
    if (!attr_done) {
        cudaFuncSetAttribute(k2_lstm, cudaFuncAttributeMaxDynamicSharedMemorySize,
                             K2_SMEM_BYTES);
        cudaFuncSetAttribute(k3_emit, cudaFuncAttributeMaxDynamicSharedMemorySize,
                             K3_SMEM_BYTES);
        attr_done = true;
    }

    k0_init<<<1, 128>>>();
    k1_pregemm<<<dim3(16, L_SEQ, 2), 256>>>(sentences, embedding,
                                            W_ih_f, b_f, W_ih_b, b_b);
    k2_lstm<<<128, 256, K2_SMEM_BYTES>>>(W_hh_f, W_hh_b);
    k3_emit<<<L_SEQ, 256, K3_SMEM_BYTES>>>(W_emit, b_emit);
    k4_crf<<<BATCH, 32>>>(tags, transition);
    k5_final<<<1, 1>>>(out);
}

// round 6
// speedup vs baseline: 1.1559x; 1.1559x over previous
#include <cuda_runtime.h>
#include <cuda_bf16.h>
#include <cstdint>

#define L_SEQ 512
#define BATCH 64
#define HID   256
#define EMB   256
#define NTAG  12

// ---------------- packed fp32x2 FMA (Blackwell) ------------------------------
__device__ __forceinline__ float2 ffma2(float2 a, float2 b, float2 c) {
    float2 d;
    asm("fma.rn.f32x2 %0, %1, %2, %3;"
        : "=l"(*reinterpret_cast<unsigned long long*>(&d))
        : "l"(*reinterpret_cast<unsigned long long*>(&a)),
          "l"(*reinterpret_cast<unsigned long long*>(&b)),
          "l"(*reinterpret_cast<unsigned long long*>(&c)));
    return d;
}
__device__ __forceinline__ float2 lo2(float4 v){ return make_float2(v.x,v.y); }
__device__ __forceinline__ float2 hi2(float4 v){ return make_float2(v.z,v.w); }

// ---------------- device scratch (static: no runtime allocation) ------------
__device__ __align__(256) float g_pre [2u*L_SEQ*1024u*BATCH]; // [dir][l][j][b]
__device__ __align__(256) float g_hall[2u*L_SEQ*BATCH*HID];   // [dir][l][b][u]
__device__ __align__(256) float g_emit[L_SEQ*BATCH*NTAG];     // [l][b][t]
__device__ float    g_nll[BATCH];
__device__ unsigned g_barc[128];                              // 4 groups, padded

// ---------------- K0: reset barrier counters --------------------------------
__global__ void k0_init() {
    if (threadIdx.x < 128) g_barc[threadIdx.x] = 0u;
}

// ---------------- K1: fused gather + input GEMM + bias (packed fp32x2) ------
__global__ void __launch_bounds__(256) k1_pregemm(
    const int*   __restrict__ sentences,
    const float* __restrict__ emb,
    const float* __restrict__ Wf, const float* __restrict__ bf,
    const float* __restrict__ Wb, const float* __restrict__ bb)
{
    __shared__ __align__(16) float Xs[64*36];   // [b][k] pad36 (stride 9 f4)
    __shared__ __align__(16) float Ws[64*36];   // [j][k] pad36
    __shared__ int toks[64];

    const int jt  = blockIdx.x;   // 0..15
    const int l   = blockIdx.y;   // 0..511
    const int dir = blockIdx.z;   // 0..1
    const float* __restrict__ W    = dir ? Wb : Wf;
    const float* __restrict__ bias = dir ? bb : bf;
    const int tid = threadIdx.x;

    if (tid < 64) toks[tid] = sentences[tid * L_SEQ + l];
    __syncthreads();

    const int tx = tid & 15;
    const int ty = tid >> 4;

    float2 acc[4][4];             // [ji][bi], packed over k parity
    #pragma unroll
    for (int a = 0; a < 4; a++)
        #pragma unroll
        for (int c = 0; c < 4; c++) acc[a][c] = make_float2(0.f, 0.f);

    for (int k0 = 0; k0 < EMB; k0 += 32) {
        #pragma unroll
        for (int i = 0; i < 2; i++) {
            int e = i*256 + tid;
            int r = e >> 3;            // row 0..63
            int q = e & 7;             // k-chunk 0..7
            *(float4*)&Xs[r*36 + q*4] =
                *(const float4*)(emb + (size_t)toks[r]*EMB + k0 + q*4);
            *(float4*)&Ws[r*36 + q*4] =
                *(const float4*)(W + (size_t)(jt*64 + r)*EMB + k0 + q*4);
        }
        __syncthreads();
        const float4* Xs4 = (const float4*)Xs;   // row stride 9
        const float4* Ws4 = (const float4*)Ws;
        #pragma unroll
        for (int k4 = 0; k4 < 8; k4++) {
            float4 xv[4], wv[4];
            #pragma unroll
            for (int bi = 0; bi < 4; bi++) xv[bi] = Xs4[(ty*4 + bi)*9 + k4];
            #pragma unroll
            for (int ji = 0; ji < 4; ji++) wv[ji] = Ws4[(ji*16 + tx)*9 + k4];
            #pragma unroll
            for (int ji = 0; ji < 4; ji++)
                #pragma unroll
                for (int bi = 0; bi < 4; bi++)
                    acc[ji][bi] = ffma2(lo2(wv[ji]), lo2(xv[bi]), acc[ji][bi]);
            #pragma unroll
            for (int ji = 0; ji < 4; ji++)
                #pragma unroll
                for (int bi = 0; bi < 4; bi++)
                    acc[ji][bi] = ffma2(hi2(wv[ji]), hi2(xv[bi]), acc[ji][bi]);
        }
        __syncthreads();
    }

    size_t base = ((size_t)(dir*L_SEQ + l)*1024u + jt*64) * 64u;
    #pragma unroll
    for (int ji = 0; ji < 4; ji++) {
        int jl = ji*16 + tx;
        float bj = bias[jt*64 + jl];
        float4 o;
        o.x = acc[ji][0].x + acc[ji][0].y + bj;
        o.y = acc[ji][1].x + acc[ji][1].y + bj;
        o.z = acc[ji][2].x + acc[ji][2].y + bj;
        o.w = acc[ji][3].x + acc[ji][3].y + bj;
        *(float4*)(g_pre + base + (size_t)jl*64 + ty*4) = o;
    }
}

// ---------------- K2: persistent bi-directional LSTM (packed fp32x2) --------
#define K2_SMEM_BYTES ((2080 + 2112)*16 + 288*4)   // 68224

__device__ __forceinline__ void group_barrier(unsigned* ctr, unsigned target) {
    __syncthreads();
    if (threadIdx.x == 0) {
        unsigned one = 1u;
        asm volatile("red.release.gpu.global.add.u32 [%0], %1;"
                     :: "l"(ctr), "r"(one) : "memory");
        unsigned v;
        do {
            asm volatile("ld.acquire.gpu.global.u32 %0, [%1];"
                         : "=r"(v) : "l"(ctr) : "memory");
        } while (v < target);
    }
    __syncthreads();
}

__global__ void __launch_bounds__(256, 1) k2_lstm(
    const float* __restrict__ Whhf, const float* __restrict__ Whhb)
{
    extern __shared__ __align__(16) float4 sm4[];
    float4* Wsh  = sm4;                  // [(gate*8+uu)*65 + kk4]  32x65
    float4* hsh  = sm4 + 2080;           // [kk4*33 + b]            64x33
    float*  hnew = (float*)(sm4 + 2080 + 2112);   // [b*9 + u]

    const int tid  = threadIdx.x;
    const int bid  = blockIdx.x;
    const int dir  = bid >> 6;
    const int sub  = bid & 63;
    const int u0   = (sub >> 1) * 8;
    const int bt   = sub & 1;
    const int b0   = bt * 32;
    const int lane = tid & 31;
    const int w    = tid >> 5;
    const int u    = u0 + w;
    const int b    = b0 + lane;
    unsigned* ctr  = &g_barc[(dir*2 + bt) * 32];

    const float* __restrict__ Whh = dir ? Whhb : Whhf;
    float*       hall = g_hall + (size_t)dir * (L_SEQ*BATCH*HID);
    const float* gpre = g_pre  + (size_t)dir * ((size_t)L_SEQ*1024u*BATCH);

    // persistent W_hh slice: 32 rows (4 gates x 8 u) x 256 k, float4 over k
    #pragma unroll
    for (int i = 0; i < 8; i++) {
        int e = i*256 + tid;       // 0..2047
        int row = e >> 6;          // 0..31
        int kk4 = e & 63;
        int gate = row >> 3, uu = row & 7;
        Wsh[row*65 + kk4] =
            *(const float4*)(Whh + (size_t)(gate*256 + u0 + uu)*HID + kk4*4);
    }

    const float4* w0p = Wsh + (0*8 + w)*65;
    const float4* w1p = Wsh + (1*8 + w)*65;
    const float4* w2p = Wsh + (2*8 + w)*65;
    const float4* w3p = Wsh + (3*8 + w)*65;

    float c = 0.f;

    for (int s = 0; s < L_SEQ; s++) {
        const int l = dir ? (L_SEQ-1 - s) : s;
        __syncthreads();   // prior hsh consumers done (also covers W init)

        if (s > 0) {
            const int lp = dir ? (l+1) : (l-1);
            const float* hp = hall + ((size_t)lp*BATCH + b0)*HID;
            #pragma unroll
            for (int i = 0; i < 8; i++) {
                int e   = i*256 + tid;
                int bb  = e >> 6;
                int kk4 = e & 63;
                hsh[kk4*33 + bb] = *(const float4*)(hp + bb*HID + kk4*4);
            }
        }
        const float* gp = gpre + (size_t)l*1024u*64u;
        float gi = gp[(0*256+u)*64 + b];
        float gf = gp[(1*256+u)*64 + b];
        float gg = gp[(2*256+u)*64 + b];
        float go = gp[(3*256+u)*64 + b];
        __syncthreads();

        if (s > 0) {
            float2 a0 = make_float2(0.f,0.f), a1 = a0, a2 = a0, a3 = a0;
            #pragma unroll 8
            for (int kk4 = 0; kk4 < 64; kk4++) {
                float4 h4 = hsh[kk4*33 + lane];
                float2 hl = lo2(h4), hh = hi2(h4);
                float4 w0v = w0p[kk4], w1v = w1p[kk4],
                       w2v = w2p[kk4], w3v = w3p[kk4];
                a0 = ffma2(lo2(w0v), hl, a0);
                a1 = ffma2(lo2(w1v), hl, a1);
                a2 = ffma2(lo2(w2v), hl, a2);
                a3 = ffma2(lo2(w3v), hl, a3);
                a0 = ffma2(hi2(w0v), hh, a0);
                a1 = ffma2(hi2(w1v), hh, a1);
                a2 = ffma2(hi2(w2v), hh, a2);
                a3 = ffma2(hi2(w3v), hh, a3);
            }
            gi += a0.x + a0.y; gf += a1.x + a1.y;
            gg += a2.x + a2.y; go += a3.x + a3.y;
        }

        float si = 1.f/(1.f + __expf(-gi));
        float sf = 1.f/(1.f + __expf(-gf));
        float so = 1.f/(1.f + __expf(-go));
        c = sf*c + si*tanhf(gg);
        float h = so*tanhf(c);

        hnew[lane*9 + w] = h;
        __syncthreads();
        {
            int bb = tid >> 3, ww = tid & 7;
            hall[((size_t)l*BATCH + b0 + bb)*HID + u0 + ww] = hnew[bb*9 + ww];
        }
        group_barrier(ctr, 32u*(unsigned)(s+1));
    }
}

// ---------------- K3: emit = [h_f, h_b] @ W_emit^T + b (packed) -------------
#define K3_SMEM_BYTES ((64*516 + NTAG*512 + 16) * 4)   // 156736

__global__ void __launch_bounds__(256) k3_emit(
    const float* __restrict__ W_emit, const float* __restrict__ b_emit)
{
    extern __shared__ __align__(16) float sm[];
    float* hs = sm;                    // [b][516] (129 float4/row)
    float* Ws = sm + 64*516;           // [t][512]
    float* bs = Ws + NTAG*512;

    const int l   = blockIdx.x;
    const int tid = threadIdx.x;
    const size_t HOFF = (size_t)L_SEQ*BATCH*HID;

    for (int i = tid; i < NTAG*512; i += 256)
        Ws[i] = W_emit[i];
    if (tid < NTAG) bs[tid] = b_emit[tid];

    const float* h0 = g_hall + (size_t)l*BATCH*HID;
    #pragma unroll
    for (int i = 0; i < 32; i++) {
        int e = i*256 + tid;          // 0..8191 float4 slots
        int bb = e >> 7;              // 0..63
        int q  = e & 127;             // 0..127 float4 over 512 k
        float4 v = (q < 64)
            ? *(const float4*)(h0 + (size_t)bb*HID + q*4)
            : *(const float4*)(h0 + HOFF + (size_t)bb*HID + (q-64)*4);
        *(float4*)&hs[bb*516 + q*4] = v;
    }
    __syncthreads();

    const int b     = tid & 63;
    const int tbase = tid >> 6;        // 0..3 ; t = tbase, tbase+4, tbase+8
    const float4* hb = (const float4*)hs + b*129;
    const float4* W4 = (const float4*)Ws;
    const float4* w0 = W4 + (tbase+0)*128;
    const float4* w1 = W4 + (tbase+4)*128;
    const float4* w2 = W4 + (tbase+8)*128;

    float2 a0 = make_float2(0.f,0.f), a1 = a0, a2 = a0;
    #pragma unroll 4
    for (int k4 = 0; k4 < 128; k4++) {
        float4 h4 = hb[k4];
        float2 hl = lo2(h4), hh = hi2(h4);
        float4 v0 = w0[k4], v1 = w1[k4], v2 = w2[k4];
        a0 = ffma2(lo2(v0), hl, a0);
        a1 = ffma2(lo2(v1), hl, a1);
        a2 = ffma2(lo2(v2), hl, a2);
        a0 = ffma2(hi2(v0), hh, a0);
        a1 = ffma2(hi2(v1), hh, a1);
        a2 = ffma2(hi2(v2), hh, a2);
    }
    float* eo = g_emit + (size_t)l*BATCH*NTAG + b*NTAG;
    eo[tbase+0] = a0.x + a0.y + bs[tbase+0];
    eo[tbase+4] = a1.x + a1.y + bs[tbase+4];
    eo[tbase+8] = a2.x + a2.y + bs[tbase+8];
}

// ---------------- K4: CRF forward + gold score per batch --------------------
__global__ void __launch_bounds__(32) k4_crf(
    const int* __restrict__ tags, const float* __restrict__ trans)
{
    const int b    = blockIdx.x;
    const int lane = threadIdx.x;
    const int tc   = (lane < NTAG) ? lane : 0;

    float Ecol[NTAG];                  // exp of trans column tc
    #pragma unroll
    for (int p = 0; p < NTAG; p++) Ecol[p] = __expf(trans[p*NTAG + tc]);

    float alpha = g_emit[b*NTAG + tc];

    for (int l = 1; l < L_SEQ; l++) {
        float e_t = g_emit[(size_t)l*BATCH*NTAG + b*NTAG + tc];
        float ap[NTAG];
        #pragma unroll
        for (int p = 0; p < NTAG; p++)
            ap[p] = __shfl_sync(0xffffffffu, alpha, p);
        float m01 = fmaxf(ap[0],ap[1]),  m23 = fmaxf(ap[2],ap[3]);
        float m45 = fmaxf(ap[4],ap[5]),  m67 = fmaxf(ap[6],ap[7]);
        float m89 = fmaxf(ap[8],ap[9]),  mAB = fmaxf(ap[10],ap[11]);
        float m = fmaxf(fmaxf(fmaxf(m01,m23), fmaxf(m45,m67)),
                        fmaxf(m89,mAB));
        float ea = __expf(alpha - m);          // identical m on every lane
        float ep[NTAG];
        #pragma unroll
        for (int p = 0; p < NTAG; p++)
            ep[p] = __shfl_sync(0xffffffffu, ea, p);
        float s01 = ep[0]*Ecol[0] + ep[1]*Ecol[1];
        float s23 = ep[2]*Ecol[2] + ep[3]*Ecol[3];
        float s45 = ep[4]*Ecol[4] + ep[5]*Ecol[5];
        float s67 = ep[6]*Ecol[6] + ep[7]*Ecol[7];
        float s89 = ep[8]*Ecol[8] + ep[9]*Ecol[9];
        float sAB = ep[10]*Ecol[10] + ep[11]*Ecol[11];
        float s = ((s01+s23) + (s45+s67)) + (s89+sAB);
        alpha = m + __logf(s) + e_t;
    }

    // logZ = logsumexp over lanes 0..11
    float av = (lane < NTAG) ? alpha : -1e30f;
    float m = av;
    #pragma unroll
    for (int off = 16; off; off >>= 1)
        m = fmaxf(m, __shfl_xor_sync(0xffffffffu, m, off));
    float s = (lane < NTAG) ? __expf(av - m) : 0.f;
    #pragma unroll
    for (int off = 16; off; off >>= 1)
        s += __shfl_xor_sync(0xffffffffu, s, off);
    float logZ = m + __logf(s);

    // gold score
    float eg = 0.f, tg = 0.f;
    for (int l = lane; l < L_SEQ; l += 32) {
        int tcur = tags[b*L_SEQ + l];
        eg += g_emit[(size_t)l*BATCH*NTAG + b*NTAG + tcur];
        if (l > 0) {
            int tprev = tags[b*L_SEQ + l - 1];
            tg += trans[tprev*NTAG + tcur];
        }
    }
    #pragma unroll
    for (int off = 16; off; off >>= 1) {
        eg += __shfl_xor_sync(0xffffffffu, eg, off);
        tg += __shfl_xor_sync(0xffffffffu, tg, off);
    }

    if (lane == 0) g_nll[b] = logZ - eg - tg;
}

// ---------------- K5: deterministic mean ------------------------------------
__global__ void k5_final(float* out) {
    if (threadIdx.x == 0) {
        float acc = 0.f;
        for (int i = 0; i < BATCH; i++) acc += g_nll[i];
        out[0] = acc / (float)BATCH;
    }
}

// ---------------- launch -----------------------------------------------------
extern "C" void kernel_launch(void* const* d_in, const int* in_sizes, int n_in,
                              void* d_out, int out_size) {
    const int*   sentences = (const int*)  d_in[0];
    const int*   tags      = (const int*)  d_in[1];
    const float* embedding = (const float*)d_in[2];
    const float* W_ih_f    = (const float*)d_in[3];
    const float* W_hh_f    = (const float*)d_in[4];
    const float* b_f       = (const float*)d_in[5];
    const float* W_ih_b    = (const float*)d_in[6];
    const float* W_hh_b    = (const float*)d_in[7];
    const float* b_b       = (const float*)d_in[8];
    const float* W_emit    = (const float*)d_in[9];
    const float* b_emit    = (const float*)d_in[10];
    const float* transition= (const float*)d_in[11];
    float* out = (float*)d_out;

    static bool attr_done = false;
    if (!attr_done) {
        cudaFuncSetAttribute(k2_lstm, cudaFuncAttributeMaxDynamicSharedMemorySize,
                             K2_SMEM_BYTES);
        cudaFuncSetAttribute(k3_emit, cudaFuncAttributeMaxDynamicSharedMemorySize,
                             K3_SMEM_BYTES);
        attr_done = true;
    }

    k0_init<<<1, 128>>>();
    k1_pregemm<<<dim3(16, L_SEQ, 2), 256>>>(sentences, embedding,
                                            W_ih_f, b_f, W_ih_b, b_b);
    k2_lstm<<<128, 256, K2_SMEM_BYTES>>>(W_hh_f, W_hh_b);
    k3_emit<<<L_SEQ, 256, K3_SMEM_BYTES>>>(W_emit, b_emit);
    k4_crf<<<BATCH, 32>>>(tags, transition);
    k5_final<<<1, 1>>>(out);
}

// round 9
// speedup vs baseline: 1.2013x; 1.0393x over previous
#include <cuda_runtime.h>
#include <cuda_bf16.h>
#include <cstdint>

#define L_SEQ 512
#define BATCH 64
#define HID   256
#define EMB   256
#define NTAG  12

// ---------------- packed fp32x2 FMA (Blackwell) ------------------------------
__device__ __forceinline__ float2 ffma2(float2 a, float2 b, float2 c) {
    float2 d;
    asm("fma.rn.f32x2 %0, %1, %2, %3;"
        : "=l"(*reinterpret_cast<unsigned long long*>(&d))
        : "l"(*reinterpret_cast<unsigned long long*>(&a)),
          "l"(*reinterpret_cast<unsigned long long*>(&b)),
          "l"(*reinterpret_cast<unsigned long long*>(&c)));
    return d;
}
__device__ __forceinline__ float2 lo2(float4 v){ return make_float2(v.x,v.y); }
__device__ __forceinline__ float2 hi2(float4 v){ return make_float2(v.z,v.w); }
__device__ __forceinline__ float tanh_fast(float x){
    float y; asm("tanh.approx.f32 %0, %1;" : "=f"(y) : "f"(x)); return y;
}
__device__ __forceinline__ float sigmoid_fast(float x){
    return __fdividef(1.f, 1.f + __expf(-x));
}

// ---------------- device scratch (static: no runtime allocation) ------------
__device__ __align__(256) float g_pre [2u*L_SEQ*1024u*BATCH]; // [dir][l][j][b]
__device__ __align__(256) float g_hall[2u*L_SEQ*BATCH*HID];   // [dir][l][b][u]
__device__ __align__(256) float g_emit[L_SEQ*BATCH*NTAG];     // [l][b][t]
__device__ float    g_nll[BATCH];
__device__ __align__(256) unsigned g_barc[128];               // 16 groups x 4

// ---------------- K0: reset barrier counters --------------------------------
__global__ void k0_init() {
    if (threadIdx.x < 128) g_barc[threadIdx.x] = 0u;
}

// ---------------- K1: fused gather + input GEMM + bias (packed fp32x2) ------
__global__ void __launch_bounds__(256) k1_pregemm(
    const int*   __restrict__ sentences,
    const float* __restrict__ emb,
    const float* __restrict__ Wf, const float* __restrict__ bf,
    const float* __restrict__ Wb, const float* __restrict__ bb)
{
    __shared__ __align__(16) float Xs[64*36];   // [b][k] pad36 (stride 9 f4)
    __shared__ __align__(16) float Ws[64*36];   // [j][k] pad36
    __shared__ int toks[64];

    const int jt  = blockIdx.x;   // 0..15
    const int l   = blockIdx.y;   // 0..511
    const int dir = blockIdx.z;   // 0..1
    const float* __restrict__ W    = dir ? Wb : Wf;
    const float* __restrict__ bias = dir ? bb : bf;
    const int tid = threadIdx.x;

    if (tid < 64) toks[tid] = sentences[tid * L_SEQ + l];
    __syncthreads();

    const int tx = tid & 15;
    const int ty = tid >> 4;

    float2 acc[4][4];
    #pragma unroll
    for (int a = 0; a < 4; a++)
        #pragma unroll
        for (int c = 0; c < 4; c++) acc[a][c] = make_float2(0.f, 0.f);

    for (int k0 = 0; k0 < EMB; k0 += 32) {
        #pragma unroll
        for (int i = 0; i < 2; i++) {
            int e = i*256 + tid;
            int r = e >> 3;
            int q = e & 7;
            *(float4*)&Xs[r*36 + q*4] =
                *(const float4*)(emb + (size_t)toks[r]*EMB + k0 + q*4);
            *(float4*)&Ws[r*36 + q*4] =
                *(const float4*)(W + (size_t)(jt*64 + r)*EMB + k0 + q*4);
        }
        __syncthreads();
        const float4* Xs4 = (const float4*)Xs;
        const float4* Ws4 = (const float4*)Ws;
        #pragma unroll
        for (int k4 = 0; k4 < 8; k4++) {
            float4 xv[4], wv[4];
            #pragma unroll
            for (int bi = 0; bi < 4; bi++) xv[bi] = Xs4[(ty*4 + bi)*9 + k4];
            #pragma unroll
            for (int ji = 0; ji < 4; ji++) wv[ji] = Ws4[(ji*16 + tx)*9 + k4];
            #pragma unroll
            for (int ji = 0; ji < 4; ji++)
                #pragma unroll
                for (int bi = 0; bi < 4; bi++)
                    acc[ji][bi] = ffma2(lo2(wv[ji]), lo2(xv[bi]), acc[ji][bi]);
            #pragma unroll
            for (int ji = 0; ji < 4; ji++)
                #pragma unroll
                for (int bi = 0; bi < 4; bi++)
                    acc[ji][bi] = ffma2(hi2(wv[ji]), hi2(xv[bi]), acc[ji][bi]);
        }
        __syncthreads();
    }

    size_t base = ((size_t)(dir*L_SEQ + l)*1024u + jt*64) * 64u;
    #pragma unroll
    for (int ji = 0; ji < 4; ji++) {
        int jl = ji*16 + tx;
        float bj = bias[jt*64 + jl];
        float4 o;
        o.x = acc[ji][0].x + acc[ji][0].y + bj;
        o.y = acc[ji][1].x + acc[ji][1].y + bj;
        o.z = acc[ji][2].x + acc[ji][2].y + bj;
        o.w = acc[ji][3].x + acc[ji][3].y + bj;
        *(float4*)(g_pre + base + (size_t)jl*64 + ty*4) = o;
    }
}

// ---------------- K2: persistent bi-directional LSTM ------------------------
// 128 CTAs: dir(2) x utile(8, 32 u each) x btile(8, 8 b each).
// Group = (dir, btile): 16 groups of 8 CTAs.  W slice 128KB persistent in smem.
// Warp covers 4 u x 8 b (lane: ul=lane>>3, bl=lane&7).
#define K2_SMEM_BYTES ((8320 + 576)*16 + 8*33*4)   // 143392

__device__ __forceinline__ void group_barrier4(unsigned* ctr, int slot,
                                               unsigned target) {
    __syncthreads();
    if (threadIdx.x == 0) {
        asm volatile("red.release.gpu.global.add.u32 [%0], %1;"
                     :: "l"(ctr + slot), "r"(1u) : "memory");
        unsigned a, b, c, d;
        do {
            asm volatile("ld.acquire.gpu.global.v4.u32 {%0,%1,%2,%3}, [%4];"
                         : "=r"(a), "=r"(b), "=r"(c), "=r"(d)
                         : "l"(ctr) : "memory");
        } while (a < target || b < target || c < target || d < target);
    }
    __syncthreads();
}

__global__ void __launch_bounds__(256, 1) k2_lstm(
    const float* __restrict__ Whhf, const float* __restrict__ Whhb)
{
    extern __shared__ __align__(16) float4 sm4[];
    float4* Wsh  = sm4;                  // [(gate*32+uu)*65 + kk4]  128x65
    float4* hsh  = sm4 + 8320;           // [kk4*9 + bb]             64x9
    float*  hnew = (float*)(sm4 + 8320 + 576);    // [bb*33 + uu]    8x33

    const int tid   = threadIdx.x;
    const int bid   = blockIdx.x;
    const int dir   = bid >> 6;
    const int sub   = bid & 63;
    const int utile = sub >> 3;          // 0..7
    const int btile = sub & 7;           // 0..7
    const int u0    = utile * 32;
    const int b0    = btile * 8;
    const int lane  = tid & 31;
    const int w     = tid >> 5;
    const int ul    = lane >> 3;         // 0..3
    const int bl    = lane & 7;          // 0..7
    const int uloc  = w*4 + ul;          // 0..31
    const int u     = u0 + uloc;
    const int b     = b0 + bl;
    unsigned* ctr   = &g_barc[(dir*8 + btile) * 4];
    const int slot  = utile & 3;

    const float* __restrict__ Whh = dir ? Whhb : Whhf;
    float*       hall = g_hall + (size_t)dir * (L_SEQ*BATCH*HID);
    const float* gpre = g_pre  + (size_t)dir * ((size_t)L_SEQ*1024u*BATCH);

    // persistent W_hh slice: 128 rows (4 gates x 32 u) x 256 k, float4 over k
    #pragma unroll
    for (int i = 0; i < 32; i++) {
        int e = i*256 + tid;       // 0..8191
        int row = e >> 6;          // 0..127
        int kk4 = e & 63;
        int gate = row >> 5, uu = row & 31;
        Wsh[row*65 + kk4] =
            *(const float4*)(Whh + (size_t)(gate*256 + u0 + uu)*HID + kk4*4);
    }

    const float4* w0p = Wsh + (0*32 + uloc)*65;
    const float4* w1p = Wsh + (1*32 + uloc)*65;
    const float4* w2p = Wsh + (2*32 + uloc)*65;
    const float4* w3p = Wsh + (3*32 + uloc)*65;

    float c = 0.f;
    int l = dir ? (L_SEQ-1) : 0;
    // preload x-part for s=0
    const float* gp = gpre + (size_t)l*65536u;
    float gi = gp[(0*256+u)*64 + b];
    float gf = gp[(1*256+u)*64 + b];
    float gg = gp[(2*256+u)*64 + b];
    float go = gp[(3*256+u)*64 + b];

    for (int s = 0; s < L_SEQ; s++) {
        if (s > 0) {
            const int lp = dir ? (l+1) : (l-1);
            const float* hp = hall + ((size_t)lp*BATCH + b0)*HID;
            // stage half 0 (kk4 0..31): 256 f4 = one pass
            {
                int bb  = tid >> 5;
                int kk4 = tid & 31;
                hsh[kk4*9 + bb] = *(const float4*)(hp + bb*HID + kk4*4);
            }
            __syncthreads();
            // issue stage half 1, then compute half 0 while it lands
            {
                int bb  = tid >> 5;
                int kk4 = 32 + (tid & 31);
                hsh[kk4*9 + bb] = *(const float4*)(hp + bb*HID + kk4*4);
            }
            float2 a0 = make_float2(0.f,0.f), a1 = a0, a2 = a0, a3 = a0;
            #pragma unroll 4
            for (int kk4 = 0; kk4 < 32; kk4++) {
                float4 h4 = hsh[kk4*9 + bl];
                float2 hl = lo2(h4), hh = hi2(h4);
                float4 w0v = w0p[kk4], w1v = w1p[kk4],
                       w2v = w2p[kk4], w3v = w3p[kk4];
                a0 = ffma2(lo2(w0v), hl, a0);
                a1 = ffma2(lo2(w1v), hl, a1);
                a2 = ffma2(lo2(w2v), hl, a2);
                a3 = ffma2(lo2(w3v), hl, a3);
                a0 = ffma2(hi2(w0v), hh, a0);
                a1 = ffma2(hi2(w1v), hh, a1);
                a2 = ffma2(hi2(w2v), hh, a2);
                a3 = ffma2(hi2(w3v), hh, a3);
            }
            __syncthreads();
            #pragma unroll 4
            for (int kk4 = 32; kk4 < 64; kk4++) {
                float4 h4 = hsh[kk4*9 + bl];
                float2 hl = lo2(h4), hh = hi2(h4);
                float4 w0v = w0p[kk4], w1v = w1p[kk4],
                       w2v = w2p[kk4], w3v = w3p[kk4];
                a0 = ffma2(lo2(w0v), hl, a0);
                a1 = ffma2(lo2(w1v), hl, a1);
                a2 = ffma2(lo2(w2v), hl, a2);
                a3 = ffma2(lo2(w3v), hl, a3);
                a0 = ffma2(hi2(w0v), hh, a0);
                a1 = ffma2(hi2(w1v), hh, a1);
                a2 = ffma2(hi2(w2v), hh, a2);
                a3 = ffma2(hi2(w3v), hh, a3);
            }
            gi += a0.x + a0.y; gf += a1.x + a1.y;
            gg += a2.x + a2.y; go += a3.x + a3.y;
        }

        float si = sigmoid_fast(gi);
        float sf = sigmoid_fast(gf);
        float so = sigmoid_fast(go);
        c = sf*c + si*tanh_fast(gg);
        float h = so*tanh_fast(c);

        // transpose via smem then coalesced global store (32 f32 = 128B rows)
        hnew[bl*33 + uloc] = h;
        __syncthreads();
        {
            int bb = tid >> 5, uu = tid & 31;
            hall[((size_t)l*BATCH + b0 + bb)*HID + u0 + uu] = hnew[bb*33 + uu];
        }

        // prefetch x-part for next step (overlaps barrier)
        if (s + 1 < L_SEQ) {
            int ln = dir ? (L_SEQ-2 - s) : (s+1);
            const float* gp2 = gpre + (size_t)ln*65536u;
            gi = gp2[(0*256+u)*64 + b];
            gf = gp2[(1*256+u)*64 + b];
            gg = gp2[(2*256+u)*64 + b];
            go = gp2[(3*256+u)*64 + b];
            l = ln;
        }
        group_barrier4(ctr, slot, 2u*(unsigned)(s+1));
    }
}

// ---------------- K3: emit = [h_f, h_b] @ W_emit^T + b (packed) -------------
#define K3_SMEM_BYTES ((32*516 + NTAG*512 + 16) * 4)   // 90688

__global__ void __launch_bounds__(128) k3_emit(
    const float* __restrict__ W_emit, const float* __restrict__ b_emit)
{
    extern __shared__ __align__(16) float sm[];
    float* hs = sm;                    // [b][516] (129 float4/row), 32 b
    float* Ws = sm + 32*516;           // [t][512]
    float* bs = Ws + NTAG*512;

    const int l   = blockIdx.x;
    const int bh  = blockIdx.y;        // 0..1 : batch half
    const int tid = threadIdx.x;
    const size_t HOFF = (size_t)L_SEQ*BATCH*HID;

    #pragma unroll
    for (int i = 0; i < 12; i++) {
        int e = i*128 + tid;           // 1536 f4 total
        ((float4*)Ws)[e] = ((const float4*)W_emit)[e];
    }
    if (tid < NTAG) bs[tid] = b_emit[tid];

    const float* h0 = g_hall + ((size_t)l*BATCH + bh*32)*HID;
    const float* h1 = h0 + HOFF;
    #pragma unroll
    for (int bb = 0; bb < 32; bb++) {
        int q = tid;                   // 0..127 f4 over 512 k
        float4 v = (q < 64)
            ? *(const float4*)(h0 + (size_t)bb*HID + q*4)
            : *(const float4*)(h1 + (size_t)bb*HID + (q-64)*4);
        *(float4*)&hs[bb*516 + q*4] = v;
    }
    __syncthreads();

    const int b     = tid & 31;
    const int tbase = tid >> 5;        // 0..3 ; t = tbase, tbase+4, tbase+8
    const float4* hb = (const float4*)hs + b*129;
    const float4* W4 = (const float4*)Ws;
    const float4* w0 = W4 + (tbase+0)*128;
    const float4* w1 = W4 + (tbase+4)*128;
    const float4* w2 = W4 + (tbase+8)*128;

    float2 a0 = make_float2(0.f,0.f), a1 = a0, a2 = a0;
    #pragma unroll 4
    for (int k4 = 0; k4 < 128; k4++) {
        float4 h4 = hb[k4];
        float2 hl = lo2(h4), hh = hi2(h4);
        float4 v0 = w0[k4], v1 = w1[k4], v2 = w2[k4];
        a0 = ffma2(lo2(v0), hl, a0);
        a1 = ffma2(lo2(v1), hl, a1);
        a2 = ffma2(lo2(v2), hl, a2);
        a0 = ffma2(hi2(v0), hh, a0);
        a1 = ffma2(hi2(v1), hh, a1);
        a2 = ffma2(hi2(v2), hh, a2);
    }
    float* eo = g_emit + (size_t)l*BATCH*NTAG + (bh*32 + b)*NTAG;
    eo[tbase+0] = a0.x + a0.y + bs[tbase+0];
    eo[tbase+4] = a1.x + a1.y + bs[tbase+4];
    eo[tbase+8] = a2.x + a2.y + bs[tbase+8];
}

// ---------------- K4: CRF forward + gold score per batch --------------------
__global__ void __launch_bounds__(32) k4_crf(
    const int* __restrict__ tags, const float* __restrict__ trans)
{
    const int b    = blockIdx.x;
    const int lane = threadIdx.x;
    const int tc   = (lane < NTAG) ? lane : 0;

    float Ecol[NTAG];                  // exp of trans column tc
    #pragma unroll
    for (int p = 0; p < NTAG; p++) Ecol[p] = __expf(trans[p*NTAG + tc]);

    float alpha = g_emit[b*NTAG + tc];

    for (int l = 1; l < L_SEQ; l++) {
        float e_t = g_emit[(size_t)l*BATCH*NTAG + b*NTAG + tc];
        float ap[NTAG];
        #pragma unroll
        for (int p = 0; p < NTAG; p++)
            ap[p] = __shfl_sync(0xffffffffu, alpha, p);
        float m01 = fmaxf(ap[0],ap[1]),  m23 = fmaxf(ap[2],ap[3]);
        float m45 = fmaxf(ap[4],ap[5]),  m67 = fmaxf(ap[6],ap[7]);
        float m89 = fmaxf(ap[8],ap[9]),  mAB = fmaxf(ap[10],ap[11]);
        float m = fmaxf(fmaxf(fmaxf(m01,m23), fmaxf(m45,m67)),
                        fmaxf(m89,mAB));
        float ea = __expf(alpha - m);
        float ep[NTAG];
        #pragma unroll
        for (int p = 0; p < NTAG; p++)
            ep[p] = __shfl_sync(0xffffffffu, ea, p);
        float s01 = ep[0]*Ecol[0] + ep[1]*Ecol[1];
        float s23 = ep[2]*Ecol[2] + ep[3]*Ecol[3];
        float s45 = ep[4]*Ecol[4] + ep[5]*Ecol[5];
        float s67 = ep[6]*Ecol[6] + ep[7]*Ecol[7];
        float s89 = ep[8]*Ecol[8] + ep[9]*Ecol[9];
        float sAB = ep[10]*Ecol[10] + ep[11]*Ecol[11];
        float s = ((s01+s23) + (s45+s67)) + (s89+sAB);
        alpha = m + __logf(s) + e_t;
    }

    float av = (lane < NTAG) ? alpha : -1e30f;
    float m = av;
    #pragma unroll
    for (int off = 16; off; off >>= 1)
        m = fmaxf(m, __shfl_xor_sync(0xffffffffu, m, off));
    float s = (lane < NTAG) ? __expf(av - m) : 0.f;
    #pragma unroll
    for (int off = 16; off; off >>= 1)
        s += __shfl_xor_sync(0xffffffffu, s, off);
    float logZ = m + __logf(s);

    float eg = 0.f, tg = 0.f;
    for (int l = lane; l < L_SEQ; l += 32) {
        int tcur = tags[b*L_SEQ + l];
        eg += g_emit[(size_t)l*BATCH*NTAG + b*NTAG + tcur];
        if (l > 0) {
            int tprev = tags[b*L_SEQ + l - 1];
            tg += trans[tprev*NTAG + tcur];
        }
    }
    #pragma unroll
    for (int off = 16; off; off >>= 1) {
        eg += __shfl_xor_sync(0xffffffffu, eg, off);
        tg += __shfl_xor_sync(0xffffffffu, tg, off);
    }

    if (lane == 0) g_nll[b] = logZ - eg - tg;
}

// ---------------- K5: deterministic mean ------------------------------------
__global__ void k5_final(float* out) {
    if (threadIdx.x == 0) {
        float acc = 0.f;
        for (int i = 0; i < BATCH; i++) acc += g_nll[i];
        out[0] = acc / (float)BATCH;
    }
}

// ---------------- launch -----------------------------------------------------
extern "C" void kernel_launch(void* const* d_in, const int* in_sizes, int n_in,
                              void* d_out, int out_size) {
    const int*   sentences = (const int*)  d_in[0];
    const int*   tags      = (const int*)  d_in[1];
    const float* embedding = (const float*)d_in[2];
    const float* W_ih_f    = (const float*)d_in[3];
    const float* W_hh_f    = (const float*)d_in[4];
    const float* b_f       = (const float*)d_in[5];
    const float* W_ih_b    = (const float*)d_in[6];
    const float* W_hh_b    = (const float*)d_in[7];
    const float* b_b       = (const float*)d_in[8];
    const float* W_emit    = (const float*)d_in[9];
    const float* b_emit    = (const float*)d_in[10];
    const float* transition= (const float*)d_in[11];
    float* out = (float*)d_out;

    static bool attr_done = false;
    if (!attr_done) {
        cudaFuncSetAttribute(k2_lstm, cudaFuncAttributeMaxDynamicSharedMemorySize,
                             K2_SMEM_BYTES);
        cudaFuncSetAttribute(k3_emit, cudaFuncAttributeMaxDynamicSharedMemorySize,
                             K3_SMEM_BYTES);
        attr_done = true;
    }

    k0_init<<<1, 128>>>();
    k1_pregemm<<<dim3(16, L_SEQ, 2), 256>>>(sentences, embedding,
                                            W_ih_f, b_f, W_ih_b, b_b);
    k2_lstm<<<128, 256, K2_SMEM_BYTES>>>(W_hh_f, W_hh_b);
    k3_emit<<<dim3(L_SEQ, 2), 128, K3_SMEM_BYTES>>>(W_emit, b_emit);
    k4_crf<<<BATCH, 32>>>(tags, transition);
    k5_final<<<1, 1>>>(out);
}

// round 10
// speedup vs baseline: 1.4394x; 1.1982x over previous
#include <cuda_runtime.h>
#include <cuda_bf16.h>
#include <cstdint>

#define L_SEQ 512
#define BATCH 64
#define HID   256
#define EMB   256
#define NTAG  12

// ---------------- packed fp32x2 FMA (Blackwell) ------------------------------
__device__ __forceinline__ float2 ffma2(float2 a, float2 b, float2 c) {
    float2 d;
    asm("fma.rn.f32x2 %0, %1, %2, %3;"
        : "=l"(*reinterpret_cast<unsigned long long*>(&d))
        : "l"(*reinterpret_cast<unsigned long long*>(&a)),
          "l"(*reinterpret_cast<unsigned long long*>(&b)),
          "l"(*reinterpret_cast<unsigned long long*>(&c)));
    return d;
}
__device__ __forceinline__ float2 lo2(float4 v){ return make_float2(v.x,v.y); }
__device__ __forceinline__ float2 hi2(float4 v){ return make_float2(v.z,v.w); }
__device__ __forceinline__ float tanh_fast(float x){
    float y; asm("tanh.approx.f32 %0, %1;" : "=f"(y) : "f"(x)); return y;
}
__device__ __forceinline__ float sigmoid_fast(float x){
    return __fdividef(1.f, 1.f + __expf(-x));
}

// ---------------- device scratch (static: no runtime allocation) ------------
__device__ __align__(256) float g_pre [2u*L_SEQ*1024u*BATCH]; // [dir][l][j][b]
__device__ __align__(256) float g_hall[2u*L_SEQ*BATCH*HID];   // [dir][l][b][u]
__device__ __align__(256) float g_emit[L_SEQ*BATCH*NTAG];     // [l][b][t]
__device__ float    g_nll[BATCH];
__device__ __align__(256) unsigned g_barc[128];               // 16 groups x 4

// ---------------- K0: reset barrier counters --------------------------------
__global__ void k0_init() {
    if (threadIdx.x < 128) g_barc[threadIdx.x] = 0u;
}

// ---------------- probe: no-op launch to steer ncu's sampled position -------
__global__ void kprobe() {}

// ---------------- K1: fused gather + input GEMM + bias (packed fp32x2) ------
__global__ void __launch_bounds__(256) k1_pregemm(
    const int*   __restrict__ sentences,
    const float* __restrict__ emb,
    const float* __restrict__ Wf, const float* __restrict__ bf,
    const float* __restrict__ Wb, const float* __restrict__ bb)
{
    __shared__ __align__(16) float Xs[64*36];   // [b][k] pad36 (stride 9 f4)
    __shared__ __align__(16) float Ws[64*36];   // [j][k] pad36
    __shared__ int toks[64];

    const int jt  = blockIdx.x;   // 0..15
    const int l   = blockIdx.y;   // 0..511
    const int dir = blockIdx.z;   // 0..1
    const float* __restrict__ W    = dir ? Wb : Wf;
    const float* __restrict__ bias = dir ? bb : bf;
    const int tid = threadIdx.x;

    if (tid < 64) toks[tid] = sentences[tid * L_SEQ + l];
    __syncthreads();

    const int tx = tid & 15;
    const int ty = tid >> 4;

    float2 acc[4][4];
    #pragma unroll
    for (int a = 0; a < 4; a++)
        #pragma unroll
        for (int c = 0; c < 4; c++) acc[a][c] = make_float2(0.f, 0.f);

    for (int k0 = 0; k0 < EMB; k0 += 32) {
        #pragma unroll
        for (int i = 0; i < 2; i++) {
            int e = i*256 + tid;
            int r = e >> 3;
            int q = e & 7;
            *(float4*)&Xs[r*36 + q*4] =
                *(const float4*)(emb + (size_t)toks[r]*EMB + k0 + q*4);
            *(float4*)&Ws[r*36 + q*4] =
                *(const float4*)(W + (size_t)(jt*64 + r)*EMB + k0 + q*4);
        }
        __syncthreads();
        const float4* Xs4 = (const float4*)Xs;
        const float4* Ws4 = (const float4*)Ws;
        #pragma unroll
        for (int k4 = 0; k4 < 8; k4++) {
            float4 xv[4], wv[4];
            #pragma unroll
            for (int bi = 0; bi < 4; bi++) xv[bi] = Xs4[(ty*4 + bi)*9 + k4];
            #pragma unroll
            for (int ji = 0; ji < 4; ji++) wv[ji] = Ws4[(ji*16 + tx)*9 + k4];
            #pragma unroll
            for (int ji = 0; ji < 4; ji++)
                #pragma unroll
                for (int bi = 0; bi < 4; bi++)
                    acc[ji][bi] = ffma2(lo2(wv[ji]), lo2(xv[bi]), acc[ji][bi]);
            #pragma unroll
            for (int ji = 0; ji < 4; ji++)
                #pragma unroll
                for (int bi = 0; bi < 4; bi++)
                    acc[ji][bi] = ffma2(hi2(wv[ji]), hi2(xv[bi]), acc[ji][bi]);
        }
        __syncthreads();
    }

    size_t base = ((size_t)(dir*L_SEQ + l)*1024u + jt*64) * 64u;
    #pragma unroll
    for (int ji = 0; ji < 4; ji++) {
        int jl = ji*16 + tx;
        float bj = bias[jt*64 + jl];
        float4 o;
        o.x = acc[ji][0].x + acc[ji][0].y + bj;
        o.y = acc[ji][1].x + acc[ji][1].y + bj;
        o.z = acc[ji][2].x + acc[ji][2].y + bj;
        o.w = acc[ji][3].x + acc[ji][3].y + bj;
        *(float4*)(g_pre + base + (size_t)jl*64 + ty*4) = o;
    }
}

// ---------------- K2: persistent bi-directional LSTM ------------------------
// 128 CTAs: dir(2) x utile(8, 32 u each) x btile(8, 8 b each), 256 threads.
// Warp = 8u x 8b, lane = (ul 0..7, bq 0..3) owning batches bq and bq+4.
// Warps split k in halves (kh = w>>2); smem partial-sum merge.
// W slice 128KB persistent; h exchanged via global + 4-slot atomic barrier.
#define K2_SMEM_F4 (8320 + 576 + 264)
#define K2_SMEM_BYTES (K2_SMEM_F4 * 16)   // 146560

__global__ void __launch_bounds__(256, 1) k2_lstm(
    const float* __restrict__ Whhf, const float* __restrict__ Whhb)
{
    extern __shared__ __align__(16) float4 sm4[];
    float4* Wsh  = sm4;                         // [(gate*32+uu)*65 + kk4]
    float4* hsh  = sm4 + 8320;                  // [kk4*9 + bb]
    float*  psum = (float*)(sm4 + 8320 + 576);  // [ug*264 + b*33 + g*8 + ul]

    const int tid   = threadIdx.x;
    const int bid   = blockIdx.x;
    const int dir   = bid >> 6;
    const int sub   = bid & 63;
    const int utile = sub >> 3;          // 0..7
    const int btile = sub & 7;           // 0..7
    const int u0    = utile * 32;
    const int b0    = btile * 8;
    const int lane  = tid & 31;
    const int w     = tid >> 5;
    const int ug    = w & 3;             // u-group within CTA
    const int kh    = w >> 2;            // k-half 0/1
    const int ul    = lane >> 2;         // 0..7
    const int bq    = lane & 3;          // 0..3 (owns bq and bq+4)
    const int uloc  = ug*8 + ul;         // 0..31
    const int u     = u0 + uloc;
    unsigned* ctr   = &g_barc[(dir*8 + btile) * 4];
    const int slot  = utile & 3;

    const float* __restrict__ Whh = dir ? Whhb : Whhf;
    float*       hall = g_hall + (size_t)dir * (L_SEQ*BATCH*HID);
    const float* gpre = g_pre  + (size_t)dir * ((size_t)L_SEQ*1024u*BATCH);

    // persistent W_hh slice: 128 rows (4 gates x 32 u) x 256 k, float4 over k
    #pragma unroll
    for (int i = 0; i < 32; i++) {
        int e = i*256 + tid;
        int row = e >> 6;          // 0..127
        int kk4 = e & 63;
        int gate = row >> 5, uu = row & 31;
        Wsh[row*65 + kk4] =
            *(const float4*)(Whh + (size_t)(gate*256 + u0 + uu)*HID + kk4*4);
    }

    const float4* w0p = Wsh + (0*32 + uloc)*65;
    const float4* w1p = Wsh + (1*32 + uloc)*65;
    const float4* w2p = Wsh + (2*32 + uloc)*65;
    const float4* w3p = Wsh + (3*32 + uloc)*65;
    const int kk_lo = kh*32, kk_hi = kh*32 + 32;

    float c0 = 0.f, c1 = 0.f;
    int l = dir ? (L_SEQ-1) : 0;

    // preload x-part for s=0 (kh0 warps carry it)
    float gv[4][2];
    if (kh == 0) {
        const float* gp = gpre + (size_t)l*65536u;
        #pragma unroll
        for (int g = 0; g < 4; g++) {
            gv[g][0] = gp[(g*256+u)*64 + b0 + bq];
            gv[g][1] = gp[(g*256+u)*64 + b0 + bq + 4];
        }
    }
    __syncthreads();   // W slice visible

    for (int s = 0; s < L_SEQ; s++) {
        float pg[4][2];
        if (s > 0) {
            float2 acc[4][2];
            #pragma unroll
            for (int g = 0; g < 4; g++) {
                acc[g][0] = make_float2(0.f,0.f);
                acc[g][1] = make_float2(0.f,0.f);
            }
            #pragma unroll 4
            for (int kk4 = kk_lo; kk4 < kk_hi; kk4++) {
                float4 ha = hsh[kk4*9 + bq];
                float4 hb = hsh[kk4*9 + bq + 4];
                float4 w0v = w0p[kk4], w1v = w1p[kk4],
                       w2v = w2p[kk4], w3v = w3p[kk4];
                float2 hal = lo2(ha), hah = hi2(ha);
                float2 hbl = lo2(hb), hbh = hi2(hb);
                acc[0][0] = ffma2(lo2(w0v), hal, acc[0][0]);
                acc[1][0] = ffma2(lo2(w1v), hal, acc[1][0]);
                acc[2][0] = ffma2(lo2(w2v), hal, acc[2][0]);
                acc[3][0] = ffma2(lo2(w3v), hal, acc[3][0]);
                acc[0][1] = ffma2(lo2(w0v), hbl, acc[0][1]);
                acc[1][1] = ffma2(lo2(w1v), hbl, acc[1][1]);
                acc[2][1] = ffma2(lo2(w2v), hbl, acc[2][1]);
                acc[3][1] = ffma2(lo2(w3v), hbl, acc[3][1]);
                acc[0][0] = ffma2(hi2(w0v), hah, acc[0][0]);
                acc[1][0] = ffma2(hi2(w1v), hah, acc[1][0]);
                acc[2][0] = ffma2(hi2(w2v), hah, acc[2][0]);
                acc[3][0] = ffma2(hi2(w3v), hah, acc[3][0]);
                acc[0][1] = ffma2(hi2(w0v), hbh, acc[0][1]);
                acc[1][1] = ffma2(hi2(w1v), hbh, acc[1][1]);
                acc[2][1] = ffma2(hi2(w2v), hbh, acc[2][1]);
                acc[3][1] = ffma2(hi2(w3v), hbh, acc[3][1]);
            }
            #pragma unroll
            for (int g = 0; g < 4; g++) {
                pg[g][0] = acc[g][0].x + acc[g][0].y;
                pg[g][1] = acc[g][1].x + acc[g][1].y;
            }
            if (kh == 1) {
                #pragma unroll
                for (int g = 0; g < 4; g++) {
                    psum[ug*264 + bq*33      + g*8 + ul] = pg[g][0];
                    psum[ug*264 + (bq+4)*33  + g*8 + ul] = pg[g][1];
                }
            }
            __syncthreads();
            if (kh == 0) {
                #pragma unroll
                for (int g = 0; g < 4; g++) {
                    pg[g][0] += psum[ug*264 + bq*33     + g*8 + ul];
                    pg[g][1] += psum[ug*264 + (bq+4)*33 + g*8 + ul];
                }
            }
        } else {
            #pragma unroll
            for (int g = 0; g < 4; g++) { pg[g][0] = 0.f; pg[g][1] = 0.f; }
        }

        if (kh == 0) {
            float gi0 = pg[0][0] + gv[0][0], gi1 = pg[0][1] + gv[0][1];
            float gf0 = pg[1][0] + gv[1][0], gf1 = pg[1][1] + gv[1][1];
            float gg0 = pg[2][0] + gv[2][0], gg1 = pg[2][1] + gv[2][1];
            float go0 = pg[3][0] + gv[3][0], go1 = pg[3][1] + gv[3][1];
            c0 = sigmoid_fast(gf0)*c0 + sigmoid_fast(gi0)*tanh_fast(gg0);
            c1 = sigmoid_fast(gf1)*c1 + sigmoid_fast(gi1)*tanh_fast(gg1);
            float h0v = sigmoid_fast(go0)*tanh_fast(c0);
            float h1v = sigmoid_fast(go1)*tanh_fast(c1);
            float* hrow = hall + (size_t)l*BATCH*HID;
            hrow[(b0 + bq    )*HID + u] = h0v;
            hrow[(b0 + bq + 4)*HID + u] = h1v;
        }
        __syncthreads();                      // stores ordered before arrive

        if (s + 1 < L_SEQ) {
            if (tid == 0) {
                asm volatile("red.release.gpu.global.add.u32 [%0], %1;"
                             :: "l"(ctr + slot), "r"(1u) : "memory");
            }
            // prefetch x-part for next step (overlaps barrier wait)
            const int ln = dir ? (L_SEQ-2 - s) : (s+1);
            if (kh == 0) {
                const float* gp2 = gpre + (size_t)ln*65536u;
                #pragma unroll
                for (int g = 0; g < 4; g++) {
                    gv[g][0] = gp2[(g*256+u)*64 + b0 + bq];
                    gv[g][1] = gp2[(g*256+u)*64 + b0 + bq + 4];
                }
            }
            if (tid == 0) {
                unsigned target = 2u*(unsigned)(s+1);
                unsigned a, b, cc, d;
                do {
                    asm volatile("ld.acquire.gpu.global.v4.u32 {%0,%1,%2,%3}, [%4];"
                                 : "=r"(a), "=r"(b), "=r"(cc), "=r"(d)
                                 : "l"(ctr) : "memory");
                } while (a < target || b < target || cc < target || d < target);
            }
            __syncthreads();

            // stage h(l) for next step: 512 f4, 2 per thread
            const float* hp = hall + ((size_t)l*BATCH + b0)*HID;
            #pragma unroll
            for (int i = 0; i < 2; i++) {
                int e   = i*256 + tid;
                int bb  = e >> 6;
                int kk4 = e & 63;
                hsh[kk4*9 + bb] = *(const float4*)(hp + bb*HID + kk4*4);
            }
            l = ln;
            __syncthreads();
        }
    }
}

// ---------------- K3: emit = [h_f, h_b] @ W_emit^T + b (packed) -------------
#define K3_SMEM_BYTES ((32*516 + NTAG*512 + 16) * 4)   // 90688

__global__ void __launch_bounds__(128) k3_emit(
    const float* __restrict__ W_emit, const float* __restrict__ b_emit)
{
    extern __shared__ __align__(16) float sm[];
    float* hs = sm;                    // [b][516] (129 float4/row), 32 b
    float* Ws = sm + 32*516;           // [t][512]
    float* bs = Ws + NTAG*512;

    const int l   = blockIdx.x;
    const int bh  = blockIdx.y;        // 0..1 : batch half
    const int tid = threadIdx.x;
    const size_t HOFF = (size_t)L_SEQ*BATCH*HID;

    #pragma unroll
    for (int i = 0; i < 12; i++) {
        int e = i*128 + tid;
        ((float4*)Ws)[e] = ((const float4*)W_emit)[e];
    }
    if (tid < NTAG) bs[tid] = b_emit[tid];

    const float* h0 = g_hall + ((size_t)l*BATCH + bh*32)*HID;
    const float* h1 = h0 + HOFF;
    #pragma unroll
    for (int bb = 0; bb < 32; bb++) {
        int q = tid;
        float4 v = (q < 64)
            ? *(const float4*)(h0 + (size_t)bb*HID + q*4)
            : *(const float4*)(h1 + (size_t)bb*HID + (q-64)*4);
        *(float4*)&hs[bb*516 + q*4] = v;
    }
    __syncthreads();

    const int b     = tid & 31;
    const int tbase = tid >> 5;        // 0..3 ; t = tbase, tbase+4, tbase+8
    const float4* hb = (const float4*)hs + b*129;
    const float4* W4 = (const float4*)Ws;
    const float4* w0 = W4 + (tbase+0)*128;
    const float4* w1 = W4 + (tbase+4)*128;
    const float4* w2 = W4 + (tbase+8)*128;

    float2 a0 = make_float2(0.f,0.f), a1 = a0, a2 = a0;
    #pragma unroll 4
    for (int k4 = 0; k4 < 128; k4++) {
        float4 h4 = hb[k4];
        float2 hl = lo2(h4), hh = hi2(h4);
        float4 v0 = w0[k4], v1 = w1[k4], v2 = w2[k4];
        a0 = ffma2(lo2(v0), hl, a0);
        a1 = ffma2(lo2(v1), hl, a1);
        a2 = ffma2(lo2(v2), hl, a2);
        a0 = ffma2(hi2(v0), hh, a0);
        a1 = ffma2(hi2(v1), hh, a1);
        a2 = ffma2(hi2(v2), hh, a2);
    }
    float* eo = g_emit + (size_t)l*BATCH*NTAG + (bh*32 + b)*NTAG;
    eo[tbase+0] = a0.x + a0.y + bs[tbase+0];
    eo[tbase+4] = a1.x + a1.y + bs[tbase+4];
    eo[tbase+8] = a2.x + a2.y + bs[tbase+8];
}

// ---------------- K4: CRF forward + gold score per batch --------------------
__global__ void __launch_bounds__(32) k4_crf(
    const int* __restrict__ tags, const float* __restrict__ trans)
{
    const int b    = blockIdx.x;
    const int lane = threadIdx.x;
    const int tc   = (lane < NTAG) ? lane : 0;

    float Ecol[NTAG];
    #pragma unroll
    for (int p = 0; p < NTAG; p++) Ecol[p] = __expf(trans[p*NTAG + tc]);

    float alpha = g_emit[b*NTAG + tc];

    for (int l = 1; l < L_SEQ; l++) {
        float e_t = g_emit[(size_t)l*BATCH*NTAG + b*NTAG + tc];
        float ap[NTAG];
        #pragma unroll
        for (int p = 0; p < NTAG; p++)
            ap[p] = __shfl_sync(0xffffffffu, alpha, p);
        float m01 = fmaxf(ap[0],ap[1]),  m23 = fmaxf(ap[2],ap[3]);
        float m45 = fmaxf(ap[4],ap[5]),  m67 = fmaxf(ap[6],ap[7]);
        float m89 = fmaxf(ap[8],ap[9]),  mAB = fmaxf(ap[10],ap[11]);
        float m = fmaxf(fmaxf(fmaxf(m01,m23), fmaxf(m45,m67)),
                        fmaxf(m89,mAB));
        float ea = __expf(alpha - m);
        float ep[NTAG];
        #pragma unroll
        for (int p = 0; p < NTAG; p++)
            ep[p] = __shfl_sync(0xffffffffu, ea, p);
        float s01 = ep[0]*Ecol[0] + ep[1]*Ecol[1];
        float s23 = ep[2]*Ecol[2] + ep[3]*Ecol[3];
        float s45 = ep[4]*Ecol[4] + ep[5]*Ecol[5];
        float s67 = ep[6]*Ecol[6] + ep[7]*Ecol[7];
        float s89 = ep[8]*Ecol[8] + ep[9]*Ecol[9];
        float sAB = ep[10]*Ecol[10] + ep[11]*Ecol[11];
        float s = ((s01+s23) + (s45+s67)) + (s89+sAB);
        alpha = m + __logf(s) + e_t;
    }

    float av = (lane < NTAG) ? alpha : -1e30f;
    float m = av;
    #pragma unroll
    for (int off = 16; off; off >>= 1)
        m = fmaxf(m, __shfl_xor_sync(0xffffffffu, m, off));
    float s = (lane < NTAG) ? __expf(av - m) : 0.f;
    #pragma unroll
    for (int off = 16; off; off >>= 1)
        s += __shfl_xor_sync(0xffffffffu, s, off);
    float logZ = m + __logf(s);

    float eg = 0.f, tg = 0.f;
    for (int l = lane; l < L_SEQ; l += 32) {
        int tcur = tags[b*L_SEQ + l];
        eg += g_emit[(size_t)l*BATCH*NTAG + b*NTAG + tcur];
        if (l > 0) {
            int tprev = tags[b*L_SEQ + l - 1];
            tg += trans[tprev*NTAG + tcur];
        }
    }
    #pragma unroll
    for (int off = 16; off; off >>= 1) {
        eg += __shfl_xor_sync(0xffffffffu, eg, off);
        tg += __shfl_xor_sync(0xffffffffu, tg, off);
    }

    if (lane == 0) g_nll[b] = logZ - eg - tg;
}

// ---------------- K5: mean (warp-parallel, deterministic) --------------------
__global__ void __launch_bounds__(32) k5_final(float* out) {
    int lane = threadIdx.x;
    float a = g_nll[lane] + g_nll[lane + 32];
    #pragma unroll
    for (int off = 16; off; off >>= 1)
        a += __shfl_xor_sync(0xffffffffu, a, off);
    if (lane == 0) out[0] = a / (float)BATCH;
}

// ---------------- launch -----------------------------------------------------
extern "C" void kernel_launch(void* const* d_in, const int* in_sizes, int n_in,
                              void* d_out, int out_size) {
    const int*   sentences = (const int*)  d_in[0];
    const int*   tags      = (const int*)  d_in[1];
    const float* embedding = (const float*)d_in[2];
    const float* W_ih_f    = (const float*)d_in[3];
    const float* W_hh_f    = (const float*)d_in[4];
    const float* b_f       = (const float*)d_in[5];
    const float* W_ih_b    = (const float*)d_in[6];
    const float* W_hh_b    = (const float*)d_in[7];
    const float* b_b       = (const float*)d_in[8];
    const float* W_emit    = (const float*)d_in[9];
    const float* b_emit    = (const float*)d_in[10];
    const float* transition= (const float*)d_in[11];
    float* out = (float*)d_out;

    static bool attr_done = false;
    if (!attr_done) {
        cudaFuncSetAttribute(k2_lstm, cudaFuncAttributeMaxDynamicSharedMemorySize,
                             K2_SMEM_BYTES);
        cudaFuncSetAttribute(k3_emit, cudaFuncAttributeMaxDynamicSharedMemorySize,
                             K3_SMEM_BYTES);
        attr_done = true;
    }

    k0_init<<<1, 128>>>();                                   // pos 0
    k1_pregemm<<<dim3(16, L_SEQ, 2), 256>>>(sentences, embedding,
                                            W_ih_f, b_f, W_ih_b, b_b);  // pos 1
    kprobe<<<1, 32>>>();                                     // pos 2 (ncu aim)
    k2_lstm<<<128, 256, K2_SMEM_BYTES>>>(W_hh_f, W_hh_b);    // pos 3 <- sampled
    k3_emit<<<dim3(L_SEQ, 2), 128, K3_SMEM_BYTES>>>(W_emit, b_emit);
    k4_crf<<<BATCH, 32>>>(tags, transition);
    k5_final<<<1, 32>>>(out);
}